// round 2
// baseline (speedup 1.0000x reference)
#include <cuda_runtime.h>

// Causal scaled-dot-product attention, B=4 H=16 S=2048 D=64, fp32.
// Flash-attention style: one CTA per (q-tile of 64 rows, head). Online softmax.
// Only k-tiles <= q-tile are processed (causal skip).
// Round 2: identical algorithm to Round 1 (infra failed; no data to act on).

#define SEQ      2048
#define DH       64
#define NTILE    64
#define NTHREADS 256
#define NQTILES  (SEQ / NTILE)   // 32
#define NBH      64              // B*H

// shared-memory strides (in floats)
#define SQ 65   // Q: scalar access, conflict-free (bank = row + d mod 32)
#define SK 65   // K: same
#define SP 68   // P: float4 reads (16B-aligned rows), conflict-free scalar writes
#define SV 64   // V: float4 reads, lanes step 16B -> conflict-free

#define SMEM_FLOATS (NTILE*SQ + NTILE*SK + NTILE*SP + NTILE*SV)
#define SMEM_BYTES  (SMEM_FLOATS * 4)

__global__ __launch_bounds__(NTHREADS, 3)
void fa_fp32_kernel(const float* __restrict__ Qg_all,
                    const float* __restrict__ Kg_all,
                    const float* __restrict__ Vg_all,
                    float* __restrict__ Og_all)
{
    extern __shared__ float smem[];
    float* Qs = smem;                    // [64][SQ]
    float* Ks = Qs + NTILE * SQ;         // [64][SK]
    float* Ps = Ks + NTILE * SK;         // [64][SP]
    float* Vs = Ps + NTILE * SP;         // [64][SV]

    const int qTile = blockIdx.x;        // 0..31
    const int bh    = blockIdx.y;        // 0..63
    const int tid   = threadIdx.x;
    const int rg    = tid >> 4;          // 0..15 : row group
    const int c     = tid & 15;          // 0..15 : column lane
    const int r0    = rg << 2;           // first of 4 q rows owned

    const float scale = 0.125f;          // 1/sqrt(64)

    const size_t base = (size_t)bh * SEQ * DH;
    const float* Qg = Qg_all + base + (size_t)qTile * NTILE * DH;
    const float* Kg = Kg_all + base;
    const float* Vg = Vg_all + base;
    float*       Og = Og_all + base + (size_t)qTile * NTILE * DH;

    // ---- load Q tile (pre-scaled) ----
    #pragma unroll
    for (int it = 0; it < (NTILE * (DH/4)) / NTHREADS; it++) {
        int i   = tid + it * NTHREADS;
        int row = i >> 4;
        int d4  = i & 15;
        float4 v = ((const float4*)(Qg + row * DH))[d4];
        float* dst = Qs + row * SQ + d4 * 4;
        dst[0] = v.x * scale; dst[1] = v.y * scale;
        dst[2] = v.z * scale; dst[3] = v.w * scale;
    }

    float acc[4][4];
    float m_i[4], l_i[4];
    #pragma unroll
    for (int i = 0; i < 4; i++) {
        m_i[i] = -1e30f; l_i[i] = 0.f;
        #pragma unroll
        for (int j = 0; j < 4; j++) acc[i][j] = 0.f;
    }

    const int nk = qTile + 1;            // causal: tiles 0..qTile
    for (int jt = 0; jt < nk; jt++) {
        __syncthreads();                 // previous iteration finished reading smem

        // ---- load K tile (stride-65 rows) and V tile (stride-64 rows) ----
        #pragma unroll
        for (int it = 0; it < (NTILE * (DH/4)) / NTHREADS; it++) {
            int i   = tid + it * NTHREADS;
            int row = i >> 4;
            int d4  = i & 15;
            float4 v = ((const float4*)(Kg + (size_t)(jt * NTILE + row) * DH))[d4];
            float* dst = Ks + row * SK + d4 * 4;
            dst[0] = v.x; dst[1] = v.y; dst[2] = v.z; dst[3] = v.w;
        }
        #pragma unroll
        for (int it = 0; it < (NTILE * (DH/4)) / NTHREADS; it++) {
            int i   = tid + it * NTHREADS;
            int row = i >> 4;
            int d4  = i & 15;
            ((float4*)(Vs + row * SV))[d4] =
                ((const float4*)(Vg + (size_t)(jt * NTILE + row) * DH))[d4];
        }
        __syncthreads();

        // ---- S = Q K^T : thread owns rows r0..r0+3, cols c+16j ----
        float s[4][4];
        #pragma unroll
        for (int i = 0; i < 4; i++)
            #pragma unroll
            for (int j = 0; j < 4; j++) s[i][j] = 0.f;

        #pragma unroll 16
        for (int d = 0; d < DH; d++) {
            float qd[4], kd[4];
            #pragma unroll
            for (int i = 0; i < 4; i++) qd[i] = Qs[(r0 + i) * SQ + d];
            #pragma unroll
            for (int j = 0; j < 4; j++) kd[j] = Ks[(c + 16 * j) * SK + d];
            #pragma unroll
            for (int i = 0; i < 4; i++)
                #pragma unroll
                for (int j = 0; j < 4; j++)
                    s[i][j] = fmaf(qd[i], kd[j], s[i][j]);
        }

        // ---- causal mask on diagonal tile ----
        if (jt == qTile) {
            #pragma unroll
            for (int i = 0; i < 4; i++)
                #pragma unroll
                for (int j = 0; j < 4; j++)
                    if (c + 16 * j > r0 + i) s[i][j] = -1e30f;
        }

        // ---- online softmax (rows shared by 16 consecutive lanes) ----
        float corr[4];
        #pragma unroll
        for (int i = 0; i < 4; i++) {
            float mx = fmaxf(fmaxf(s[i][0], s[i][1]), fmaxf(s[i][2], s[i][3]));
            mx = fmaxf(mx, __shfl_xor_sync(0xffffffffu, mx, 1));
            mx = fmaxf(mx, __shfl_xor_sync(0xffffffffu, mx, 2));
            mx = fmaxf(mx, __shfl_xor_sync(0xffffffffu, mx, 4));
            mx = fmaxf(mx, __shfl_xor_sync(0xffffffffu, mx, 8));
            float mnew = fmaxf(m_i[i], mx);
            corr[i] = __expf(m_i[i] - mnew);
            m_i[i] = mnew;

            float rs = 0.f;
            #pragma unroll
            for (int j = 0; j < 4; j++) {
                float p = __expf(s[i][j] - mnew);
                s[i][j] = p;
                rs += p;
            }
            rs += __shfl_xor_sync(0xffffffffu, rs, 1);
            rs += __shfl_xor_sync(0xffffffffu, rs, 2);
            rs += __shfl_xor_sync(0xffffffffu, rs, 4);
            rs += __shfl_xor_sync(0xffffffffu, rs, 8);
            l_i[i] = l_i[i] * corr[i] + rs;
            #pragma unroll
            for (int j = 0; j < 4; j++) acc[i][j] *= corr[i];
        }

        // ---- write P to smem (conflict-free: lane c owns distinct banks) ----
        #pragma unroll
        for (int i = 0; i < 4; i++)
            #pragma unroll
            for (int j = 0; j < 4; j++)
                Ps[(r0 + i) * SP + c + 16 * j] = s[i][j];
        __syncthreads();

        // ---- O += P V : thread owns rows r0..r0+3, d-cols 4c..4c+3 ----
        #pragma unroll 4
        for (int k4 = 0; k4 < 16; k4++) {
            float4 p4[4];
            #pragma unroll
            for (int i = 0; i < 4; i++)
                p4[i] = *(const float4*)(Ps + (r0 + i) * SP + k4 * 4);
            float4 v4[4];
            #pragma unroll
            for (int kk = 0; kk < 4; kk++)
                v4[kk] = *(const float4*)(Vs + (k4 * 4 + kk) * SV + c * 4);
            #pragma unroll
            for (int i = 0; i < 4; i++) {
                float pi0 = p4[i].x, pi1 = p4[i].y, pi2 = p4[i].z, pi3 = p4[i].w;
                acc[i][0] = fmaf(pi0, v4[0].x, acc[i][0]);
                acc[i][1] = fmaf(pi0, v4[0].y, acc[i][1]);
                acc[i][2] = fmaf(pi0, v4[0].z, acc[i][2]);
                acc[i][3] = fmaf(pi0, v4[0].w, acc[i][3]);
                acc[i][0] = fmaf(pi1, v4[1].x, acc[i][0]);
                acc[i][1] = fmaf(pi1, v4[1].y, acc[i][1]);
                acc[i][2] = fmaf(pi1, v4[1].z, acc[i][2]);
                acc[i][3] = fmaf(pi1, v4[1].w, acc[i][3]);
                acc[i][0] = fmaf(pi2, v4[2].x, acc[i][0]);
                acc[i][1] = fmaf(pi2, v4[2].y, acc[i][1]);
                acc[i][2] = fmaf(pi2, v4[2].z, acc[i][2]);
                acc[i][3] = fmaf(pi2, v4[2].w, acc[i][3]);
                acc[i][0] = fmaf(pi3, v4[3].x, acc[i][0]);
                acc[i][1] = fmaf(pi3, v4[3].y, acc[i][1]);
                acc[i][2] = fmaf(pi3, v4[3].z, acc[i][2]);
                acc[i][3] = fmaf(pi3, v4[3].w, acc[i][3]);
            }
        }
    }

    // ---- epilogue: normalize and store (float4, coalesced) ----
    #pragma unroll
    for (int i = 0; i < 4; i++) {
        float inv = 1.0f / l_i[i];
        float4 o;
        o.x = acc[i][0] * inv;
        o.y = acc[i][1] * inv;
        o.z = acc[i][2] * inv;
        o.w = acc[i][3] * inv;
        *((float4*)(Og + (r0 + i) * DH + 4 * c)) = o;
    }
}

extern "C" void kernel_launch(void* const* d_in, const int* in_sizes, int n_in,
                              void* d_out, int out_size)
{
    (void)in_sizes; (void)n_in; (void)out_size;
    const float* Q = (const float*)d_in[0];
    const float* K = (const float*)d_in[1];
    const float* V = (const float*)d_in[2];
    // d_in[3] is the causal mask; it is tril(ones) by construction, handled analytically.
    float* O = (float*)d_out;

    static int smem_attr_set = 0;
    if (!smem_attr_set) {
        cudaFuncSetAttribute(fa_fp32_kernel,
                             cudaFuncAttributeMaxDynamicSharedMemorySize, SMEM_BYTES);
        smem_attr_set = 1;
    }

    dim3 grid(NQTILES, NBH);
    fa_fp32_kernel<<<grid, NTHREADS, SMEM_BYTES>>>(Q, K, V, O);
}

// round 3
// speedup vs baseline: 1.3197x; 1.3197x over previous
#include <cuda_runtime.h>

// Causal SDPA, B=4 H=16 S=2048 D=64, fp32 in/out.
// TF32 tensor-core flash attention with 3xTF32 error compensation (hi/lo split)
// on both Q.K^T and P.V  ->  rel_err ~1e-6 while running on the tensor pipe.
//
// CTA: 256 threads = 8 warps, q-tile = 128 rows (16 rows/warp), k-tile = 64 keys.
// smem: Qhi/Qlo [128][68], Khi/Klo [64][68], Vhi/Vlo [64][68] (pad-68 rows ->
// conflict-free ldmatrix).  mma.sync m16n8k8 tf32.

#define SEQ    2048
#define DH     64
#define QTILE  128
#define KTILE  64
#define STRIDE 68

#define Q_FLOATS (128 * STRIDE)   // 8704
#define K_FLOATS (64 * STRIDE)    // 4352
#define SMEM_FLOATS (2*Q_FLOATS + 4*K_FLOATS)
#define SMEM_BYTES  (SMEM_FLOATS * 4)

__device__ __forceinline__ unsigned f2tf_bits(float x) {
    unsigned r; asm("cvt.rna.tf32.f32 %0, %1;" : "=r"(r) : "f"(x)); return r;
}
__device__ __forceinline__ float tf_hi(float x) { return __uint_as_float(f2tf_bits(x)); }

__device__ __forceinline__ void ldsm4(unsigned &r0, unsigned &r1, unsigned &r2, unsigned &r3,
                                      unsigned addr) {
    asm volatile("ldmatrix.sync.aligned.m8n8.x4.shared.b16 {%0,%1,%2,%3}, [%4];"
                 : "=r"(r0), "=r"(r1), "=r"(r2), "=r"(r3) : "r"(addr));
}
__device__ __forceinline__ void mma8(float c[4], const unsigned a[4], unsigned b0, unsigned b1) {
    asm volatile("mma.sync.aligned.m16n8k8.row.col.f32.tf32.tf32.f32 "
                 "{%0,%1,%2,%3},{%4,%5,%6,%7},{%8,%9},{%0,%1,%2,%3};"
                 : "+f"(c[0]), "+f"(c[1]), "+f"(c[2]), "+f"(c[3])
                 : "r"(a[0]), "r"(a[1]), "r"(a[2]), "r"(a[3]), "r"(b0), "r"(b1));
}

__global__ __launch_bounds__(256)
void fa_tc_kernel(const float* __restrict__ Qg_all, const float* __restrict__ Kg_all,
                  const float* __restrict__ Vg_all, float* __restrict__ Og_all)
{
    extern __shared__ float sm[];
    float* Qhi = sm;
    float* Qlo = Qhi + Q_FLOATS;
    float* Khi = Qlo + Q_FLOATS;
    float* Klo = Khi + K_FLOATS;
    float* Vhi = Klo + K_FLOATS;
    float* Vlo = Vhi + K_FLOATS;

    const int qt   = (int)gridDim.x - 1 - (int)blockIdx.x;  // heavy q-tiles first
    const int bh   = blockIdx.y;
    const int tid  = threadIdx.x;
    const int warp = tid >> 5;
    const int lane = tid & 31;
    const int r    = lane >> 2;          // 0..7 fragment row
    const int cc   = lane & 3;           // 0..3 fragment col pair

    const size_t base = (size_t)bh * SEQ * DH;
    const float* Qg = Qg_all + base + (size_t)qt * QTILE * DH;
    const float* Kg = Kg_all + base;
    const float* Vg = Vg_all + base;
    float*       Og = Og_all + base;

    // ---- load Q tile (scaled by 1/8, split hi/lo) ----
    #pragma unroll
    for (int it = 0; it < 8; it++) {
        int idx = tid + it * 256;
        int row = idx >> 4, d4 = (idx & 15) * 4;
        float4 v = *(const float4*)(Qg + (size_t)row * DH + d4);
        v.x *= 0.125f; v.y *= 0.125f; v.z *= 0.125f; v.w *= 0.125f;
        float hx = tf_hi(v.x), hy = tf_hi(v.y), hz = tf_hi(v.z), hw = tf_hi(v.w);
        int o = row * STRIDE + d4;
        *(float4*)(Qhi + o) = make_float4(hx, hy, hz, hw);
        *(float4*)(Qlo + o) = make_float4(tf_hi(v.x - hx), tf_hi(v.y - hy),
                                          tf_hi(v.z - hz), tf_hi(v.w - hw));
    }

    // ldmatrix base addresses (x4 pattern: lane&15 -> row, lane>>4 -> 16B chunk)
    const int lrow = lane & 15;
    const int lchk = (lane >> 4) * 4;
    const unsigned aQhi = (unsigned)__cvta_generic_to_shared(Qhi + (16 * warp + lrow) * STRIDE + lchk);
    const unsigned aQlo = aQhi + Q_FLOATS * 4u;
    const unsigned aKhi = (unsigned)__cvta_generic_to_shared(Khi + lrow * STRIDE + lchk);
    const unsigned aKlo = aKhi + K_FLOATS * 4u;

    float S[8][4], Oa[8][4];
    float m0 = -1e30f, m1 = -1e30f, l0 = 0.f, l1 = 0.f;
    #pragma unroll
    for (int nt = 0; nt < 8; nt++) {
        Oa[nt][0] = 0.f; Oa[nt][1] = 0.f; Oa[nt][2] = 0.f; Oa[nt][3] = 0.f;
    }

    const int nkt   = 2 * qt + 2;
    const int qbase = qt * QTILE + 16 * warp;
    const int sA = cc >> 1, sB = (cc >> 1) + 2;   // quad shuffle sources

    for (int kt = 0; kt < nkt; kt++) {
        __syncthreads();
        // ---- load K and V tiles (split hi/lo), coalesced float4 ----
        #pragma unroll
        for (int it = 0; it < 4; it++) {
            int idx = tid + it * 256;
            int row = idx >> 4, d4 = (idx & 15) * 4;
            float4 v = *(const float4*)(Kg + (size_t)(kt * KTILE + row) * DH + d4);
            float hx = tf_hi(v.x), hy = tf_hi(v.y), hz = tf_hi(v.z), hw = tf_hi(v.w);
            int o = row * STRIDE + d4;
            *(float4*)(Khi + o) = make_float4(hx, hy, hz, hw);
            *(float4*)(Klo + o) = make_float4(tf_hi(v.x - hx), tf_hi(v.y - hy),
                                              tf_hi(v.z - hz), tf_hi(v.w - hw));
        }
        #pragma unroll
        for (int it = 0; it < 4; it++) {
            int idx = tid + it * 256;
            int row = idx >> 4, d4 = (idx & 15) * 4;
            float4 v = *(const float4*)(Vg + (size_t)(kt * KTILE + row) * DH + d4);
            float hx = tf_hi(v.x), hy = tf_hi(v.y), hz = tf_hi(v.z), hw = tf_hi(v.w);
            int o = row * STRIDE + d4;
            *(float4*)(Vhi + o) = make_float4(hx, hy, hz, hw);
            *(float4*)(Vlo + o) = make_float4(tf_hi(v.x - hx), tf_hi(v.y - hy),
                                              tf_hi(v.z - hz), tf_hi(v.w - hw));
        }
        __syncthreads();

        // ---- S = Q K^T (3-pass tf32 split) ----
        #pragma unroll
        for (int nt = 0; nt < 8; nt++) {
            S[nt][0] = 0.f; S[nt][1] = 0.f; S[nt][2] = 0.f; S[nt][3] = 0.f;
        }
        #pragma unroll
        for (int kb = 0; kb < 8; kb++) {
            unsigned Ah[4], Al[4];
            ldsm4(Ah[0], Ah[1], Ah[2], Ah[3], aQhi + kb * 32u);
            ldsm4(Al[0], Al[1], Al[2], Al[3], aQlo + kb * 32u);
            #pragma unroll
            for (int np = 0; np < 4; np++) {
                unsigned off = (unsigned)(np * 16 * STRIDE + kb * 8) * 4u;
                unsigned bh0, bh1, bh2, bh3, bl0, bl1, bl2, bl3;
                ldsm4(bh0, bh1, bh2, bh3, aKhi + off);
                ldsm4(bl0, bl1, bl2, bl3, aKlo + off);
                mma8(S[2*np],   Ah, bh0, bh2);
                mma8(S[2*np],   Ah, bl0, bl2);
                mma8(S[2*np],   Al, bh0, bh2);
                mma8(S[2*np+1], Ah, bh1, bh3);
                mma8(S[2*np+1], Ah, bl1, bl3);
                mma8(S[2*np+1], Al, bh1, bh3);
            }
        }

        // ---- causal mask (only possible on the last two k-tiles) ----
        if (kt >= 2 * qt) {
            #pragma unroll
            for (int nt = 0; nt < 8; nt++) {
                int k0 = kt * KTILE + nt * 8 + 2 * cc;
                int row0 = qbase + r;
                if (k0     > row0)     S[nt][0] = -1e30f;
                if (k0 + 1 > row0)     S[nt][1] = -1e30f;
                if (k0     > row0 + 8) S[nt][2] = -1e30f;
                if (k0 + 1 > row0 + 8) S[nt][3] = -1e30f;
            }
        }

        // ---- online softmax (rows r and r+8; reduce across quad lanes) ----
        float mx0 = -1e30f, mx1 = -1e30f;
        #pragma unroll
        for (int nt = 0; nt < 8; nt++) {
            mx0 = fmaxf(mx0, fmaxf(S[nt][0], S[nt][1]));
            mx1 = fmaxf(mx1, fmaxf(S[nt][2], S[nt][3]));
        }
        mx0 = fmaxf(mx0, __shfl_xor_sync(0xffffffffu, mx0, 1));
        mx0 = fmaxf(mx0, __shfl_xor_sync(0xffffffffu, mx0, 2));
        mx1 = fmaxf(mx1, __shfl_xor_sync(0xffffffffu, mx1, 1));
        mx1 = fmaxf(mx1, __shfl_xor_sync(0xffffffffu, mx1, 2));
        float mn0 = fmaxf(m0, mx0), mn1 = fmaxf(m1, mx1);
        float cr0 = __expf(m0 - mn0), cr1 = __expf(m1 - mn1);
        m0 = mn0; m1 = mn1;
        float s0 = 0.f, s1 = 0.f;
        #pragma unroll
        for (int nt = 0; nt < 8; nt++) {
            S[nt][0] = __expf(S[nt][0] - mn0); s0 += S[nt][0];
            S[nt][1] = __expf(S[nt][1] - mn0); s0 += S[nt][1];
            S[nt][2] = __expf(S[nt][2] - mn1); s1 += S[nt][2];
            S[nt][3] = __expf(S[nt][3] - mn1); s1 += S[nt][3];
        }
        s0 += __shfl_xor_sync(0xffffffffu, s0, 1);
        s0 += __shfl_xor_sync(0xffffffffu, s0, 2);
        s1 += __shfl_xor_sync(0xffffffffu, s1, 1);
        s1 += __shfl_xor_sync(0xffffffffu, s1, 2);
        l0 = l0 * cr0 + s0;
        l1 = l1 * cr1 + s1;
        #pragma unroll
        for (int nt = 0; nt < 8; nt++) {
            Oa[nt][0] *= cr0; Oa[nt][1] *= cr0;
            Oa[nt][2] *= cr1; Oa[nt][3] *= cr1;
        }

        // ---- O += P V (3-pass tf32 split); P D-frag -> A-frag via quad shuffles ----
        #pragma unroll
        for (int kb = 0; kb < 8; kb++) {
            float d0 = S[kb][0], d1 = S[kb][1], d2 = S[kb][2], d3 = S[kb][3];
            float h0 = tf_hi(d0), h1 = tf_hi(d1), h2 = tf_hi(d2), h3 = tf_hi(d3);
            float g0 = tf_hi(d0 - h0), g1 = tf_hi(d1 - h1);
            float g2 = tf_hi(d2 - h2), g3 = tf_hi(d3 - h3);

            unsigned Ph[4], Pl[4];
            {
                float tA0 = __shfl_sync(0xffffffffu, h0, sA, 4);
                float tA1 = __shfl_sync(0xffffffffu, h1, sA, 4);
                float tB0 = __shfl_sync(0xffffffffu, h0, sB, 4);
                float tB1 = __shfl_sync(0xffffffffu, h1, sB, 4);
                float uA0 = __shfl_sync(0xffffffffu, h2, sA, 4);
                float uA1 = __shfl_sync(0xffffffffu, h3, sA, 4);
                float uB0 = __shfl_sync(0xffffffffu, h2, sB, 4);
                float uB1 = __shfl_sync(0xffffffffu, h3, sB, 4);
                Ph[0] = __float_as_uint((cc & 1) ? tA1 : tA0);
                Ph[1] = __float_as_uint((cc & 1) ? uA1 : uA0);
                Ph[2] = __float_as_uint((cc & 1) ? tB1 : tB0);
                Ph[3] = __float_as_uint((cc & 1) ? uB1 : uB0);
            }
            {
                float tA0 = __shfl_sync(0xffffffffu, g0, sA, 4);
                float tA1 = __shfl_sync(0xffffffffu, g1, sA, 4);
                float tB0 = __shfl_sync(0xffffffffu, g0, sB, 4);
                float tB1 = __shfl_sync(0xffffffffu, g1, sB, 4);
                float uA0 = __shfl_sync(0xffffffffu, g2, sA, 4);
                float uA1 = __shfl_sync(0xffffffffu, g3, sA, 4);
                float uB0 = __shfl_sync(0xffffffffu, g2, sB, 4);
                float uB1 = __shfl_sync(0xffffffffu, g3, sB, 4);
                Pl[0] = __float_as_uint((cc & 1) ? tA1 : tA0);
                Pl[1] = __float_as_uint((cc & 1) ? uA1 : uA0);
                Pl[2] = __float_as_uint((cc & 1) ? tB1 : tB0);
                Pl[3] = __float_as_uint((cc & 1) ? uB1 : uB0);
            }

            // V B-frags via scalar LDS from natural [key][d] layout:
            // b0 = V[kb*8+cc][nt*8+r], b1 = V[kb*8+cc+4][nt*8+r]
            const float* v0h = Vhi + (kb * 8 + cc) * STRIDE + r;
            const float* v1h = Vhi + (kb * 8 + cc + 4) * STRIDE + r;
            #pragma unroll
            for (int nt = 0; nt < 8; nt++) {
                unsigned vb0h = __float_as_uint(v0h[nt * 8]);
                unsigned vb1h = __float_as_uint(v1h[nt * 8]);
                unsigned vb0l = __float_as_uint(v0h[nt * 8 + K_FLOATS]);
                unsigned vb1l = __float_as_uint(v1h[nt * 8 + K_FLOATS]);
                mma8(Oa[nt], Ph, vb0h, vb1h);
                mma8(Oa[nt], Ph, vb0l, vb1l);
                mma8(Oa[nt], Pl, vb0h, vb1h);
            }
        }
    }

    // ---- epilogue: normalize, store ----
    float i0 = 1.0f / l0, i1 = 1.0f / l1;
    int row0 = qbase + r, row1 = row0 + 8;
    #pragma unroll
    for (int nt = 0; nt < 8; nt++) {
        int col = nt * 8 + 2 * cc;
        *(float2*)(Og + (size_t)row0 * DH + col) = make_float2(Oa[nt][0] * i0, Oa[nt][1] * i0);
        *(float2*)(Og + (size_t)row1 * DH + col) = make_float2(Oa[nt][2] * i1, Oa[nt][3] * i1);
    }
}

extern "C" void kernel_launch(void* const* d_in, const int* in_sizes, int n_in,
                              void* d_out, int out_size)
{
    (void)in_sizes; (void)n_in; (void)out_size;
    const float* Q = (const float*)d_in[0];
    const float* K = (const float*)d_in[1];
    const float* V = (const float*)d_in[2];
    // d_in[3] (mask) is tril(ones) by construction -> handled analytically.
    float* O = (float*)d_out;

    static int attr_set = 0;
    if (!attr_set) {
        cudaFuncSetAttribute(fa_tc_kernel,
                             cudaFuncAttributeMaxDynamicSharedMemorySize, SMEM_BYTES);
        attr_set = 1;
    }

    dim3 grid(SEQ / QTILE, 64);   // (16 q-tiles, B*H)
    fa_tc_kernel<<<grid, 256, SMEM_BYTES>>>(Q, K, V, O);
}

// round 5
// speedup vs baseline: 2.8343x; 2.1477x over previous
#include <cuda_runtime.h>
#include <cuda_bf16.h>

// Causal SDPA, B=4 H=16 S=2048 D=64, fp32 in/out.
// bf16 split (hi + lo) 3-pass tensor-core flash attention, m16n8k16.
// effective ~17-bit mantissa -> rel_err ~1e-5.
// CTA: 256 thr / 8 warps, q-tile 128 (16 rows/warp), k-tile 64.
// smem 72KB -> 2 CTAs/SM (occ 25%), ldsm-friendly stride-72 bf16 rows.
// Round 5: identical to Round 4 (infra failed twice; no data to act on).

#define SEQ   2048
#define DH    64
#define QTILE 128
#define KTILE 64
#define STRB  72                       // bf16 elems per smem row (conflict-free ldsm)

#define Q_ELE (QTILE * STRB)           // 9216
#define K_ELE (KTILE * STRB)           // 4608
#define SMEM_ELE (2*Q_ELE + 4*K_ELE)   // 36864 bf16
#define SMEM_BYTES (SMEM_ELE * 2)      // 73728 B

__device__ __forceinline__ void ldsm4(unsigned &r0, unsigned &r1, unsigned &r2, unsigned &r3,
                                      unsigned addr) {
    asm volatile("ldmatrix.sync.aligned.m8n8.x4.shared.b16 {%0,%1,%2,%3}, [%4];"
                 : "=r"(r0), "=r"(r1), "=r"(r2), "=r"(r3) : "r"(addr));
}
__device__ __forceinline__ void ldsm4t(unsigned &r0, unsigned &r1, unsigned &r2, unsigned &r3,
                                       unsigned addr) {
    asm volatile("ldmatrix.sync.aligned.m8n8.x4.trans.shared.b16 {%0,%1,%2,%3}, [%4];"
                 : "=r"(r0), "=r"(r1), "=r"(r2), "=r"(r3) : "r"(addr));
}
// D += A(16x16 bf16) * B(16x8 bf16), fp32 accum
__device__ __forceinline__ void mma16(float c[4], const unsigned a[4], unsigned b0, unsigned b1) {
    asm volatile("mma.sync.aligned.m16n8k16.row.col.f32.bf16.bf16.f32 "
                 "{%0,%1,%2,%3},{%4,%5,%6,%7},{%8,%9},{%0,%1,%2,%3};"
                 : "+f"(c[0]), "+f"(c[1]), "+f"(c[2]), "+f"(c[3])
                 : "r"(a[0]), "r"(a[1]), "r"(a[2]), "r"(a[3]), "r"(b0), "r"(b1));
}
// split (x,y) into packed bf16x2 hi and residual lo
__device__ __forceinline__ void split2(float x, float y, unsigned &hi, unsigned &lo) {
    __nv_bfloat162 h = __floats2bfloat162_rn(x, y);
    float rx = x - __bfloat162float(h.x);
    float ry = y - __bfloat162float(h.y);
    __nv_bfloat162 l = __floats2bfloat162_rn(rx, ry);
    hi = *reinterpret_cast<unsigned*>(&h);
    lo = *reinterpret_cast<unsigned*>(&l);
}

__global__ __launch_bounds__(256, 2)
void fa_bf16s_kernel(const float* __restrict__ Qg_all, const float* __restrict__ Kg_all,
                     const float* __restrict__ Vg_all, float* __restrict__ Og_all)
{
    extern __shared__ __nv_bfloat16 smb[];
    __nv_bfloat16* Qhi = smb;
    __nv_bfloat16* Qlo = Qhi + Q_ELE;
    __nv_bfloat16* Khi = Qlo + Q_ELE;
    __nv_bfloat16* Klo = Khi + K_ELE;
    __nv_bfloat16* Vhi = Klo + K_ELE;
    __nv_bfloat16* Vlo = Vhi + K_ELE;

    const int qt   = (int)gridDim.x - 1 - (int)blockIdx.x;  // heavy q-tiles first
    const int bh   = blockIdx.y;
    const int tid  = threadIdx.x;
    const int warp = tid >> 5;
    const int lane = tid & 31;
    const int r    = lane >> 2;     // frag row 0..7
    const int cc   = lane & 3;      // frag col-pair 0..3

    const size_t base = (size_t)bh * SEQ * DH;
    const float* Qg = Qg_all + base + (size_t)qt * QTILE * DH;
    const float* Kg = Kg_all + base;
    const float* Vg = Vg_all + base;
    float*       Og = Og_all + base;

    // ---- load Q tile (scaled 1/8), split into bf16 hi/lo ----
    #pragma unroll
    for (int it = 0; it < 8; it++) {
        int idx = tid + it * 256;
        int row = idx >> 4, d4 = (idx & 15) * 4;
        float4 v = *(const float4*)(Qg + (size_t)row * DH + d4);
        v.x *= 0.125f; v.y *= 0.125f; v.z *= 0.125f; v.w *= 0.125f;
        unsigned h0, l0, h1, l1;
        split2(v.x, v.y, h0, l0);
        split2(v.z, v.w, h1, l1);
        int o = row * STRB + d4;
        *(unsigned*)(Qhi + o)     = h0;  *(unsigned*)(Qhi + o + 2) = h1;
        *(unsigned*)(Qlo + o)     = l0;  *(unsigned*)(Qlo + o + 2) = l1;
    }

    // ldmatrix base addresses (x4: lane&15 -> row, lane>>4 -> 16B chunk)
    const int lrow = lane & 15;
    const int lchk = (lane >> 4) * 8;                 // bf16 elems
    const unsigned aQhi = (unsigned)__cvta_generic_to_shared(Qhi + (16 * warp + lrow) * STRB + lchk);
    const unsigned aQlo = aQhi + Q_ELE * 2u;
    const unsigned aKhi = (unsigned)__cvta_generic_to_shared(Khi + lrow * STRB + lchk);
    const unsigned aKlo = aKhi + K_ELE * 2u;
    const unsigned aVhi = (unsigned)__cvta_generic_to_shared(Vhi + lrow * STRB + lchk);
    const unsigned aVlo = aVhi + K_ELE * 2u;

    float S[8][4], Oa[8][4];
    float m0 = -1e30f, m1 = -1e30f, l0s = 0.f, l1s = 0.f;
    #pragma unroll
    for (int nt = 0; nt < 8; nt++) {
        Oa[nt][0] = 0.f; Oa[nt][1] = 0.f; Oa[nt][2] = 0.f; Oa[nt][3] = 0.f;
    }

    const int nkt   = 2 * qt + 2;
    const int qbase = qt * QTILE + 16 * warp;

    for (int kt = 0; kt < nkt; kt++) {
        __syncthreads();
        // ---- load K,V tiles, split hi/lo ----
        #pragma unroll
        for (int it = 0; it < 4; it++) {
            int idx = tid + it * 256;
            int row = idx >> 4, d4 = (idx & 15) * 4;
            float4 v = *(const float4*)(Kg + (size_t)(kt * KTILE + row) * DH + d4);
            unsigned h0, l0, h1, l1;
            split2(v.x, v.y, h0, l0);
            split2(v.z, v.w, h1, l1);
            int o = row * STRB + d4;
            *(unsigned*)(Khi + o)     = h0;  *(unsigned*)(Khi + o + 2) = h1;
            *(unsigned*)(Klo + o)     = l0;  *(unsigned*)(Klo + o + 2) = l1;
        }
        #pragma unroll
        for (int it = 0; it < 4; it++) {
            int idx = tid + it * 256;
            int row = idx >> 4, d4 = (idx & 15) * 4;
            float4 v = *(const float4*)(Vg + (size_t)(kt * KTILE + row) * DH + d4);
            unsigned h0, l0, h1, l1;
            split2(v.x, v.y, h0, l0);
            split2(v.z, v.w, h1, l1);
            int o = row * STRB + d4;
            *(unsigned*)(Vhi + o)     = h0;  *(unsigned*)(Vhi + o + 2) = h1;
            *(unsigned*)(Vlo + o)     = l0;  *(unsigned*)(Vlo + o + 2) = l1;
        }
        __syncthreads();

        // ---- S = Q K^T : 4 k16 blocks over D, 3-pass compensated ----
        #pragma unroll
        for (int nt = 0; nt < 8; nt++) {
            S[nt][0] = 0.f; S[nt][1] = 0.f; S[nt][2] = 0.f; S[nt][3] = 0.f;
        }
        #pragma unroll
        for (int kb = 0; kb < 4; kb++) {
            unsigned Ah[4], Al[4];
            ldsm4(Ah[0], Ah[1], Ah[2], Ah[3], aQhi + kb * 32u);
            ldsm4(Al[0], Al[1], Al[2], Al[3], aQlo + kb * 32u);
            #pragma unroll
            for (int np = 0; np < 4; np++) {
                unsigned off = (unsigned)(np * 16 * STRB * 2 + kb * 32);
                unsigned bh0, bh1, bh2, bh3, bl0, bl1, bl2, bl3;
                ldsm4(bh0, bh1, bh2, bh3, aKhi + off);
                ldsm4(bl0, bl1, bl2, bl3, aKlo + off);
                // keys np*16+0..7 -> S[2np] (B = {reg0, reg2}); keys +8..15 -> S[2np+1]
                mma16(S[2*np],   Ah, bh0, bh2);
                mma16(S[2*np],   Ah, bl0, bl2);
                mma16(S[2*np],   Al, bh0, bh2);
                mma16(S[2*np+1], Ah, bh1, bh3);
                mma16(S[2*np+1], Ah, bl1, bl3);
                mma16(S[2*np+1], Al, bh1, bh3);
            }
        }

        // ---- causal mask (only the last two k-tiles can clip) ----
        if (kt >= 2 * qt) {
            #pragma unroll
            for (int nt = 0; nt < 8; nt++) {
                int k0 = kt * KTILE + nt * 8 + 2 * cc;
                int row0 = qbase + r;
                if (k0     > row0)     S[nt][0] = -1e30f;
                if (k0 + 1 > row0)     S[nt][1] = -1e30f;
                if (k0     > row0 + 8) S[nt][2] = -1e30f;
                if (k0 + 1 > row0 + 8) S[nt][3] = -1e30f;
            }
        }

        // ---- online softmax ----
        float mx0 = -1e30f, mx1 = -1e30f;
        #pragma unroll
        for (int nt = 0; nt < 8; nt++) {
            mx0 = fmaxf(mx0, fmaxf(S[nt][0], S[nt][1]));
            mx1 = fmaxf(mx1, fmaxf(S[nt][2], S[nt][3]));
        }
        mx0 = fmaxf(mx0, __shfl_xor_sync(0xffffffffu, mx0, 1));
        mx0 = fmaxf(mx0, __shfl_xor_sync(0xffffffffu, mx0, 2));
        mx1 = fmaxf(mx1, __shfl_xor_sync(0xffffffffu, mx1, 1));
        mx1 = fmaxf(mx1, __shfl_xor_sync(0xffffffffu, mx1, 2));
        float mn0 = fmaxf(m0, mx0), mn1 = fmaxf(m1, mx1);
        float cr0 = __expf(m0 - mn0), cr1 = __expf(m1 - mn1);
        m0 = mn0; m1 = mn1;
        float s0 = 0.f, s1 = 0.f;
        #pragma unroll
        for (int nt = 0; nt < 8; nt++) {
            S[nt][0] = __expf(S[nt][0] - mn0); s0 += S[nt][0];
            S[nt][1] = __expf(S[nt][1] - mn0); s0 += S[nt][1];
            S[nt][2] = __expf(S[nt][2] - mn1); s1 += S[nt][2];
            S[nt][3] = __expf(S[nt][3] - mn1); s1 += S[nt][3];
        }
        s0 += __shfl_xor_sync(0xffffffffu, s0, 1);
        s0 += __shfl_xor_sync(0xffffffffu, s0, 2);
        s1 += __shfl_xor_sync(0xffffffffu, s1, 1);
        s1 += __shfl_xor_sync(0xffffffffu, s1, 2);
        l0s = l0s * cr0 + s0;
        l1s = l1s * cr1 + s1;
        #pragma unroll
        for (int nt = 0; nt < 8; nt++) {
            Oa[nt][0] *= cr0; Oa[nt][1] *= cr0;
            Oa[nt][2] *= cr1; Oa[nt][3] *= cr1;
        }

        // ---- O += P V : P D-frags pack directly into k16 A-frags ----
        #pragma unroll
        for (int kb = 0; kb < 4; kb++) {       // keys 16*kb .. 16*kb+15
            unsigned Ph[4], Pl[4];
            split2(S[2*kb][0],   S[2*kb][1],   Ph[0], Pl[0]);
            split2(S[2*kb][2],   S[2*kb][3],   Ph[1], Pl[1]);
            split2(S[2*kb+1][0], S[2*kb+1][1], Ph[2], Pl[2]);
            split2(S[2*kb+1][2], S[2*kb+1][3], Ph[3], Pl[3]);

            #pragma unroll
            for (int dp = 0; dp < 4; dp++) {   // d 16*dp .. 16*dp+15
                unsigned off = (unsigned)(kb * 16 * STRB * 2 + dp * 32);
                unsigned wh0, wh1, wh2, wh3, wl0, wl1, wl2, wl3;
                ldsm4t(wh0, wh1, wh2, wh3, aVhi + off);
                ldsm4t(wl0, wl1, wl2, wl3, aVlo + off);
                // n-block d 16dp..+7 : B = {reg0, reg1}; d +8..+15 : {reg2, reg3}
                mma16(Oa[2*dp],   Ph, wh0, wh1);
                mma16(Oa[2*dp],   Ph, wl0, wl1);
                mma16(Oa[2*dp],   Pl, wh0, wh1);
                mma16(Oa[2*dp+1], Ph, wh2, wh3);
                mma16(Oa[2*dp+1], Ph, wl2, wl3);
                mma16(Oa[2*dp+1], Pl, wh2, wh3);
            }
        }
    }

    // ---- epilogue ----
    float i0 = 1.0f / l0s, i1 = 1.0f / l1s;
    int row0 = qbase + r, row1 = row0 + 8;
    #pragma unroll
    for (int nt = 0; nt < 8; nt++) {
        int col = nt * 8 + 2 * cc;
        *(float2*)(Og + (size_t)row0 * DH + col) = make_float2(Oa[nt][0] * i0, Oa[nt][1] * i0);
        *(float2*)(Og + (size_t)row1 * DH + col) = make_float2(Oa[nt][2] * i1, Oa[nt][3] * i1);
    }
}

extern "C" void kernel_launch(void* const* d_in, const int* in_sizes, int n_in,
                              void* d_out, int out_size)
{
    (void)in_sizes; (void)n_in; (void)out_size;
    const float* Q = (const float*)d_in[0];
    const float* K = (const float*)d_in[1];
    const float* V = (const float*)d_in[2];
    // d_in[3] (mask) is tril(ones) by construction -> handled analytically.
    float* O = (float*)d_out;

    static int attr_set = 0;
    if (!attr_set) {
        cudaFuncSetAttribute(fa_bf16s_kernel,
                             cudaFuncAttributeMaxDynamicSharedMemorySize, SMEM_BYTES);
        attr_set = 1;
    }

    dim3 grid(SEQ / QTILE, 64);   // (16 q-tiles, B*H)
    fa_bf16s_kernel<<<grid, 256, SMEM_BYTES>>>(Q, K, V, O);
}